// round 6
// baseline (speedup 1.0000x reference)
#include <cuda_runtime.h>
#include <cuda_bf16.h>
#include <cstdint>

#define BATCH 4
#define SEQ   4096
#define CDIM  256
#define HEADS 4
#define HDIM  64
#define SCALE 0.125f
#define BH    (BATCH*HEADS)

// attention tiling
#define TK    64
#define KSTR  72                  // floats; 72 % 32 == 8 -> conflict-free LDS.64
#define VSTR2 68                  // float2; 68 % 16 == 4 -> conflict-free LDS.64
#define KBYTES (TK*KSTR*4)        // 18432
#define VBYTES ((TK/2)*VSTR2*8)   // 17408
#define BUFBYTES (KBYTES + VBYTES)
#define SMEM_ATTN (2*BUFBYTES)    // 71680 B

// projection GEMM tiling (tf32 mma): 128x128 tile, k-chunk 32
#define PSTR 36
#define PBUF (2*128*PSTR)
#define SMEM_PROJ (2*PBUF*4)      // 73728 B

// ---------------------------------------------------------------------------
// Scratch. q/k pair-packed along d: p(d) = (d&~7) | ((d&3)<<1) | ((d>>2)&1)
// v pair-packed along n: row j=(n>>3)*4+(n&3), comp=(n>>2)&1, float2 rows of 64
// ---------------------------------------------------------------------------
__device__ float g_q[BH * SEQ * HDIM];
__device__ float g_k[BH * SEQ * HDIM];
__device__ float g_v[BH * SEQ * HDIM];
__device__ float g_ao[BATCH * SEQ * CDIM];

// ---------------------------------------------------------------------------
__device__ __forceinline__ float tf32r(float x) {
    uint32_t u; asm("cvt.rna.tf32.f32 %0, %1;" : "=r"(u) : "f"(x));
    return __uint_as_float(u);
}
__device__ __forceinline__ uint32_t tf32bits(float x) {
    uint32_t u; asm("cvt.rna.tf32.f32 %0, %1;" : "=r"(u) : "f"(x));
    return u;
}
__device__ __forceinline__ uint32_t smem_u32(const void* p) {
    uint32_t a;
    asm("{ .reg .u64 t; cvta.to.shared.u64 t, %1; cvt.u32.u64 %0, t; }" : "=r"(a) : "l"(p));
    return a;
}
__device__ __forceinline__ void cpa16(uint32_t dst, const float* src) {
    asm volatile("cp.async.cg.shared.global [%0], [%1], 16;" :: "r"(dst), "l"(src) : "memory");
}
__device__ __forceinline__ void mma_tf32(float (&c)[4], const uint32_t (&a)[4],
                                         uint32_t b0, uint32_t b1) {
    asm("mma.sync.aligned.m16n8k8.row.col.f32.tf32.tf32.f32 "
        "{%0,%1,%2,%3}, {%4,%5,%6,%7}, {%8,%9}, {%0,%1,%2,%3};"
        : "+f"(c[0]), "+f"(c[1]), "+f"(c[2]), "+f"(c[3])
        : "r"(a[0]), "r"(a[1]), "r"(a[2]), "r"(a[3]), "r"(b0), "r"(b1));
}
__device__ __forceinline__ void permA(const float (&e)[4], uint32_t (&pa)[4], int lane) {
    uint32_t t0 = tf32bits(e[0]), t1 = tf32bits(e[1]);
    uint32_t t2 = tf32bits(e[2]), t3 = tf32bits(e[3]);
    int srcA = (lane & ~3) | ((lane & 3) >> 1);
    int srcB = srcA + 2;
    uint32_t x0 = __shfl_sync(0xffffffffu, t0, srcA);
    uint32_t x1 = __shfl_sync(0xffffffffu, t1, srcA);
    uint32_t y0 = __shfl_sync(0xffffffffu, t2, srcA);
    uint32_t y1 = __shfl_sync(0xffffffffu, t3, srcA);
    uint32_t x2 = __shfl_sync(0xffffffffu, t0, srcB);
    uint32_t x3 = __shfl_sync(0xffffffffu, t1, srcB);
    uint32_t y2 = __shfl_sync(0xffffffffu, t2, srcB);
    uint32_t y3 = __shfl_sync(0xffffffffu, t3, srcB);
    bool od = lane & 1;
    pa[0] = od ? x1 : x0;
    pa[1] = od ? y1 : y0;
    pa[2] = od ? x3 : x2;
    pa[3] = od ? y3 : y2;
}
__device__ __forceinline__ int dpack(int d) {
    return (d & ~7) | ((d & 3) << 1) | ((d >> 2) & 1);
}

// ---------------------------------------------------------------------------
// tf32 mma projection core (unchanged from R5)
// ---------------------------------------------------------------------------
struct ProjAcc { float c[2][8][4]; };

__device__ __forceinline__ void proj_core(const float* __restrict__ A,
                                          const float* __restrict__ Bm,
                                          int m0, int n0, float* smp, ProjAcc& P)
{
    const int tid = threadIdx.x, lane = tid & 31, warp = tid >> 5;
    const int g = lane >> 2, qd = lane & 3;
    const int wm = warp >> 1, wn = warp & 1;
    const uint32_t smb = smem_u32(smp);

    #pragma unroll
    for (int m = 0; m < 2; m++)
        #pragma unroll
        for (int nn = 0; nn < 8; nn++)
            #pragma unroll
            for (int i = 0; i < 4; i++) P.c[m][nn][i] = 0.f;

    auto stage = [&](int kc, int b) {
        uint32_t xb = smb + (uint32_t)(b * PBUF) * 4;
        uint32_t wb = xb + (uint32_t)(128 * PSTR) * 4;
        int k0 = kc * 32;
        #pragma unroll
        for (int p = 0; p < 4; p++) {
            int idx = p * 256 + tid;
            int r = idx >> 3, cc = idx & 7;
            cpa16(xb + (uint32_t)(r * PSTR + cc * 4) * 4, A  + (size_t)(m0 + r) * CDIM + k0 + cc * 4);
            cpa16(wb + (uint32_t)(r * PSTR + cc * 4) * 4, Bm + (size_t)(n0 + r) * CDIM + k0 + cc * 4);
        }
    };

    stage(0, 0);
    asm volatile("cp.async.commit_group;" ::: "memory");

    for (int kc = 0; kc < CDIM / 32; kc++) {
        int b = kc & 1;
        if (kc + 1 < CDIM / 32) {
            stage(kc + 1, b ^ 1);
            asm volatile("cp.async.commit_group;" ::: "memory");
            asm volatile("cp.async.wait_group 1;" ::: "memory");
        } else {
            asm volatile("cp.async.wait_group 0;" ::: "memory");
        }
        __syncthreads();

        const float* Xs = smp + b * PBUF;
        const float* Ws = Xs + 128 * PSTR;

        #pragma unroll
        for (int kk = 0; kk < 4; kk++) {
            uint32_t am[2][4];
            #pragma unroll
            for (int m = 0; m < 2; m++) {
                const float* ar = Xs + (wm * 32 + m * 16) * PSTR + kk * 8;
                am[m][0] = tf32bits(ar[(g    ) * PSTR + qd    ]);
                am[m][1] = tf32bits(ar[(g + 8) * PSTR + qd    ]);
                am[m][2] = tf32bits(ar[(g    ) * PSTR + qd + 4]);
                am[m][3] = tf32bits(ar[(g + 8) * PSTR + qd + 4]);
            }
            #pragma unroll
            for (int nn = 0; nn < 8; nn++) {
                const float* br = Ws + (wn * 64 + nn * 8 + g) * PSTR + kk * 8;
                uint32_t b0 = tf32bits(br[qd]);
                uint32_t b1 = tf32bits(br[qd + 4]);
                mma_tf32(P.c[0][nn], am[0], b0, b1);
                mma_tf32(P.c[1][nn], am[1], b0, b1);
            }
        }
        __syncthreads();
    }
}

// grid (2, 128, 3)
__global__ void __launch_bounds__(256) proj_qkv(const float* __restrict__ x,
                                                const float* __restrict__ Wq,
                                                const float* __restrict__ Wk,
                                                const float* __restrict__ Wv)
{
    extern __shared__ float smp[];
    const float* W = (blockIdx.z == 0) ? Wq : (blockIdx.z == 1) ? Wk : Wv;
    float* dst     = (blockIdx.z == 0) ? g_q : (blockIdx.z == 1) ? g_k : g_v;
    const float sc = (blockIdx.z == 0) ? SCALE : 1.0f;
    const int m0 = blockIdx.y * 128, n0 = blockIdx.x * 128;

    ProjAcc P;
    proj_core(x, W, m0, n0, smp, P);

    const int lane = threadIdx.x & 31, warp = threadIdx.x >> 5;
    const int g = lane >> 2, qd = lane & 3;
    const int wm = warp >> 1, wn = warp & 1;

    #pragma unroll
    for (int m = 0; m < 2; m++)
        #pragma unroll
        for (int rr = 0; rr < 2; rr++) {
            int mg = m0 + wm * 32 + m * 16 + g + rr * 8;
            int b = mg >> 12, n = mg & (SEQ - 1);
            #pragma unroll
            for (int nn = 0; nn < 8; nn++) {
                int col = n0 + wn * 64 + nn * 8 + qd * 2;
                int h = col >> 6, d = col & 63;
                float v0 = tf32r(P.c[m][nn][rr * 2 + 0] * sc);
                float v1 = tf32r(P.c[m][nn][rr * 2 + 1] * sc);
                size_t bh = (size_t)(b * HEADS + h);
                if (blockIdx.z < 2) {
                    // pair-packed along d
                    float* rowp = dst + (bh * SEQ + n) * HDIM;
                    rowp[dpack(d)]     = v0;
                    rowp[dpack(d + 1)] = v1;
                } else {
                    // V: pair-packed along n, float2 rows of 64
                    int jg = ((n >> 3) << 2) | (n & 3);
                    int comp = (n >> 2) & 1;
                    float* vp = dst + (bh * (SEQ / 2) + jg) * (HDIM * 2) + comp;
                    vp[d * 2]       = v0;
                    vp[(d + 1) * 2] = v1;
                }
            }
        }
}

// grid (2, 128)
__global__ void __launch_bounds__(256) proj_out(const float* __restrict__ Wp,
                                                const float* __restrict__ bp,
                                                float* __restrict__ out)
{
    extern __shared__ float smp[];
    const int m0 = blockIdx.y * 128, n0 = blockIdx.x * 128;

    ProjAcc P;
    proj_core(g_ao, Wp, m0, n0, smp, P);

    const int lane = threadIdx.x & 31, warp = threadIdx.x >> 5;
    const int g = lane >> 2, qd = lane & 3;
    const int wm = warp >> 1, wn = warp & 1;

    #pragma unroll
    for (int m = 0; m < 2; m++)
        #pragma unroll
        for (int rr = 0; rr < 2; rr++) {
            int mg = m0 + wm * 32 + m * 16 + g + rr * 8;
            #pragma unroll
            for (int nn = 0; nn < 8; nn++) {
                int col = n0 + wn * 64 + nn * 8 + qd * 2;
                float2 bb = *(const float2*)(bp + col);
                float2 v = make_float2(P.c[m][nn][rr * 2 + 0] + bb.x,
                                       P.c[m][nn][rr * 2 + 1] + bb.y);
                *(float2*)&out[(size_t)mg * CDIM + col] = v;
            }
        }
}

// ---------------------------------------------------------------------------
// tf32 mma.sync flash attention, pair-packed operands (LDS.64 fragments)
// grid = (SEQ/128, BH), block = 128, target 3 CTAs/SM
// ---------------------------------------------------------------------------
__global__ void __launch_bounds__(128, 3) attn_mma()
{
    extern __shared__ float sm[];
    const int tid = threadIdx.x, lane = tid & 31, warp = tid >> 5;
    const int g = lane >> 2, qd = lane & 3;
    const int bh = blockIdx.y, q0 = blockIdx.x * 128;

    const float2* qg2 = (const float2*)(g_q + ((size_t)bh * SEQ + q0 + warp * 32) * HDIM);
    const float*  kg  = g_k + (size_t)bh * SEQ * HDIM;
    const float*  vgp = g_v + (size_t)bh * SEQ * HDIM;   // packed: 2048 rows x 128 floats

    // persistent Q A-fragments (packed pairs: one LDG.64 -> a0,a2 / a1,a3)
    uint32_t qf[2][8][4];
    #pragma unroll
    for (int m = 0; m < 2; m++)
        #pragma unroll
        for (int kk = 0; kk < 8; kk++) {
            float2 qa = qg2[(m * 16 + g    ) * 32 + kk * 4 + qd];
            float2 qb = qg2[(m * 16 + g + 8) * 32 + kk * 4 + qd];
            qf[m][kk][0] = __float_as_uint(qa.x);
            qf[m][kk][1] = __float_as_uint(qb.x);
            qf[m][kk][2] = __float_as_uint(qa.y);
            qf[m][kk][3] = __float_as_uint(qb.y);
        }

    float o[2][8][4] = {};
    float ls[4] = {0.f, 0.f, 0.f, 0.f};

    const uint32_t smb = smem_u32(sm);

    auto stage = [&](int t4, int buf) {
        uint32_t kdst = smb + buf * BUFBYTES;
        uint32_t vdst = kdst + KBYTES;
        int j0 = t4 * TK;
        #pragma unroll
        for (int i = 0; i < 8; i++) {
            int idx = i * 128 + tid;
            int r = idx >> 4, c = idx & 15;
            cpa16(kdst + (uint32_t)(r * KSTR + c * 4) * 4, kg + (size_t)(j0 + r) * 64 + c * 4);
            int r2 = idx >> 5, c2 = idx & 31;
            cpa16(vdst + (uint32_t)(r2 * (VSTR2 * 2) + c2 * 4) * 4,
                  vgp + (size_t)(j0 / 2 + r2) * 128 + c2 * 4);
        }
    };

    stage(0, 0);
    asm volatile("cp.async.commit_group;" ::: "memory");

    for (int t = 0; t < SEQ / TK; t++) {
        int buf = t & 1;
        if (t + 1 < SEQ / TK) {
            stage(t + 1, buf ^ 1);
            asm volatile("cp.async.commit_group;" ::: "memory");
            asm volatile("cp.async.wait_group 1;" ::: "memory");
        } else {
            asm volatile("cp.async.wait_group 0;" ::: "memory");
        }
        __syncthreads();

        const float*  Ks  = sm + buf * (BUFBYTES / 4);
        const float2* Vs2 = (const float2*)(Ks + KBYTES / 4);

        for (int nn = 0; nn < 8; nn++) {
            // ---- S = Q K^T ----
            float c0[4] = {}, c1[4] = {};
            const float2* kb2 = (const float2*)Ks + (nn * 8 + g) * (KSTR / 2) + qd;
            #pragma unroll
            for (int kk = 0; kk < 8; kk++) {
                float2 b01 = kb2[kk * 4];
                uint32_t b0 = __float_as_uint(b01.x);
                uint32_t b1 = __float_as_uint(b01.y);
                mma_tf32(c0, qf[0][kk], b0, b1);
                mma_tf32(c1, qf[1][kk], b0, b1);
            }

            // ---- exp + row-sum ----
            float e0[4], e1[4];
            #pragma unroll
            for (int i = 0; i < 4; i++) { e0[i] = __expf(c0[i]); e1[i] = __expf(c1[i]); }
            ls[0] += e0[0] + e0[1];  ls[1] += e0[2] + e0[3];
            ls[2] += e1[0] + e1[1];  ls[3] += e1[2] + e1[3];

            uint32_t pa0[4], pa1[4];
            permA(e0, pa0, lane);
            permA(e1, pa1, lane);

            // ---- O += P V ----
            const float2* vb2 = Vs2 + (nn * 4 + qd) * VSTR2 + g;
            #pragma unroll
            for (int dn = 0; dn < 8; dn++) {
                float2 v01 = vb2[dn * 8];
                uint32_t b0 = __float_as_uint(v01.x);
                uint32_t b1 = __float_as_uint(v01.y);
                mma_tf32(o[0][dn], pa0, b0, b1);
                mma_tf32(o[1][dn], pa1, b0, b1);
            }
        }
        __syncthreads();
    }

    #pragma unroll
    for (int i = 0; i < 4; i++) {
        ls[i] += __shfl_xor_sync(0xffffffffu, ls[i], 1);
        ls[i] += __shfl_xor_sync(0xffffffffu, ls[i], 2);
    }

    const int b = bh >> 2, h = bh & 3;
    #pragma unroll
    for (int m = 0; m < 2; m++)
        #pragma unroll
        for (int rr = 0; rr < 2; rr++) {
            int row = q0 + warp * 32 + m * 16 + g + rr * 8;
            float iv = 1.f / ls[m * 2 + rr];
            #pragma unroll
            for (int dn = 0; dn < 8; dn++) {
                float2 v = make_float2(tf32r(o[m][dn][rr * 2 + 0] * iv),
                                       tf32r(o[m][dn][rr * 2 + 1] * iv));
                *(float2*)&g_ao[((size_t)(b * SEQ) + row) * CDIM + h * 64 + dn * 8 + qd * 2] = v;
            }
        }
}

// ---------------------------------------------------------------------------
extern "C" void kernel_launch(void* const* d_in, const int* in_sizes, int n_in,
                              void* d_out, int out_size)
{
    (void)in_sizes; (void)n_in; (void)out_size;
    const float* x  = (const float*)d_in[0];
    const float* Wq = (const float*)d_in[1];
    const float* Wk = (const float*)d_in[2];
    const float* Wv = (const float*)d_in[3];
    const float* Wp = (const float*)d_in[4];
    const float* bp = (const float*)d_in[5];
    float* out = (float*)d_out;

    cudaFuncSetAttribute(proj_qkv, cudaFuncAttributeMaxDynamicSharedMemorySize, SMEM_PROJ);
    cudaFuncSetAttribute(proj_out, cudaFuncAttributeMaxDynamicSharedMemorySize, SMEM_PROJ);
    cudaFuncSetAttribute(attn_mma, cudaFuncAttributeMaxDynamicSharedMemorySize, SMEM_ATTN);

    dim3 gq(CDIM / 128, (BATCH * SEQ) / 128, 3);
    proj_qkv<<<gq, 256, SMEM_PROJ>>>(x, Wq, Wk, Wv);

    dim3 ga(SEQ / 128, BH);
    attn_mma<<<ga, 128, SMEM_ATTN>>>();

    dim3 go(CDIM / 128, (BATCH * SEQ) / 128);
    proj_out<<<go, 256, SMEM_PROJ>>>(Wp, bp, out);
}

// round 7
// speedup vs baseline: 1.2599x; 1.2599x over previous
#include <cuda_runtime.h>
#include <cuda_bf16.h>
#include <cstdint>

#define BATCH 4
#define SEQ   4096
#define CDIM  256
#define HEADS 4
#define HDIM  64
#define SCALE 0.125f
#define BH    (BATCH*HEADS)

// attention tiling
#define TK    64
#define KSTR  72                  // floats; 72 % 32 == 8 -> conflict-free LDS.64
#define VSTR2 68                  // float2; 68 % 16 == 4 -> conflict-free LDS.64
#define KBYTES (TK*KSTR*4)        // 18432
#define VBYTES ((TK/2)*VSTR2*8)   // 17408
#define BUFBYTES (KBYTES + VBYTES)
#define SMEM_ATTN (2*BUFBYTES)    // 71680 B

// projection GEMM tiling (tf32 mma): 128x128 tile, k-chunk 32
#define PSTR 36
#define PBUF (2*128*PSTR)
#define SMEM_PROJ (2*PBUF*4)      // 73728 B

// ---------------------------------------------------------------------------
// Scratch. q/k pair-packed along d: p(d) = (d&~7) | ((d&3)<<1) | ((d>>2)&1)
// v pair-packed along n: row j=(n>>3)*4+(n&3), comp=(n>>2)&1, float2 rows of 64
// ---------------------------------------------------------------------------
__device__ float g_q[BH * SEQ * HDIM];
__device__ float g_k[BH * SEQ * HDIM];
__device__ float g_v[BH * SEQ * HDIM];
__device__ float g_ao[BATCH * SEQ * CDIM];

// ---------------------------------------------------------------------------
__device__ __forceinline__ float tf32r(float x) {
    uint32_t u; asm("cvt.rna.tf32.f32 %0, %1;" : "=r"(u) : "f"(x));
    return __uint_as_float(u);
}
__device__ __forceinline__ uint32_t tf32bits(float x) {
    uint32_t u; asm("cvt.rna.tf32.f32 %0, %1;" : "=r"(u) : "f"(x));
    return u;
}
__device__ __forceinline__ uint32_t smem_u32(const void* p) {
    uint32_t a;
    asm("{ .reg .u64 t; cvta.to.shared.u64 t, %1; cvt.u32.u64 %0, t; }" : "=r"(a) : "l"(p));
    return a;
}
__device__ __forceinline__ void cpa16(uint32_t dst, const float* src) {
    asm volatile("cp.async.cg.shared.global [%0], [%1], 16;" :: "r"(dst), "l"(src) : "memory");
}
__device__ __forceinline__ void mma_tf32(float (&c)[4], const uint32_t (&a)[4],
                                         uint32_t b0, uint32_t b1) {
    asm("mma.sync.aligned.m16n8k8.row.col.f32.tf32.tf32.f32 "
        "{%0,%1,%2,%3}, {%4,%5,%6,%7}, {%8,%9}, {%0,%1,%2,%3};"
        : "+f"(c[0]), "+f"(c[1]), "+f"(c[2]), "+f"(c[3])
        : "r"(a[0]), "r"(a[1]), "r"(a[2]), "r"(a[3]), "r"(b0), "r"(b1));
}
__device__ __forceinline__ void permA(const float (&e)[4], uint32_t (&pa)[4], int lane) {
    uint32_t t0 = tf32bits(e[0]), t1 = tf32bits(e[1]);
    uint32_t t2 = tf32bits(e[2]), t3 = tf32bits(e[3]);
    int srcA = (lane & ~3) | ((lane & 3) >> 1);
    int srcB = srcA + 2;
    uint32_t x0 = __shfl_sync(0xffffffffu, t0, srcA);
    uint32_t x1 = __shfl_sync(0xffffffffu, t1, srcA);
    uint32_t y0 = __shfl_sync(0xffffffffu, t2, srcA);
    uint32_t y1 = __shfl_sync(0xffffffffu, t3, srcA);
    uint32_t x2 = __shfl_sync(0xffffffffu, t0, srcB);
    uint32_t x3 = __shfl_sync(0xffffffffu, t1, srcB);
    uint32_t y2 = __shfl_sync(0xffffffffu, t2, srcB);
    uint32_t y3 = __shfl_sync(0xffffffffu, t3, srcB);
    bool od = lane & 1;
    pa[0] = od ? x1 : x0;
    pa[1] = od ? y1 : y0;
    pa[2] = od ? x3 : x2;
    pa[3] = od ? y3 : y2;
}
__device__ __forceinline__ int dpack(int d) {
    return (d & ~7) | ((d & 3) << 1) | ((d >> 2) & 1);
}

// ---------------------------------------------------------------------------
// tf32 mma projection core
// ---------------------------------------------------------------------------
struct ProjAcc { float c[2][8][4]; };

__device__ __forceinline__ void proj_core(const float* __restrict__ A,
                                          const float* __restrict__ Bm,
                                          int m0, int n0, float* smp, ProjAcc& P)
{
    const int tid = threadIdx.x, lane = tid & 31, warp = tid >> 5;
    const int g = lane >> 2, qd = lane & 3;
    const int wm = warp >> 1, wn = warp & 1;
    const uint32_t smb = smem_u32(smp);

    #pragma unroll
    for (int m = 0; m < 2; m++)
        #pragma unroll
        for (int nn = 0; nn < 8; nn++)
            #pragma unroll
            for (int i = 0; i < 4; i++) P.c[m][nn][i] = 0.f;

    auto stage = [&](int kc, int b) {
        uint32_t xb = smb + (uint32_t)(b * PBUF) * 4;
        uint32_t wb = xb + (uint32_t)(128 * PSTR) * 4;
        int k0 = kc * 32;
        #pragma unroll
        for (int p = 0; p < 4; p++) {
            int idx = p * 256 + tid;
            int r = idx >> 3, cc = idx & 7;
            cpa16(xb + (uint32_t)(r * PSTR + cc * 4) * 4, A  + (size_t)(m0 + r) * CDIM + k0 + cc * 4);
            cpa16(wb + (uint32_t)(r * PSTR + cc * 4) * 4, Bm + (size_t)(n0 + r) * CDIM + k0 + cc * 4);
        }
    };

    stage(0, 0);
    asm volatile("cp.async.commit_group;" ::: "memory");

    for (int kc = 0; kc < CDIM / 32; kc++) {
        int b = kc & 1;
        if (kc + 1 < CDIM / 32) {
            stage(kc + 1, b ^ 1);
            asm volatile("cp.async.commit_group;" ::: "memory");
            asm volatile("cp.async.wait_group 1;" ::: "memory");
        } else {
            asm volatile("cp.async.wait_group 0;" ::: "memory");
        }
        __syncthreads();

        const float* Xs = smp + b * PBUF;
        const float* Ws = Xs + 128 * PSTR;

        #pragma unroll
        for (int kk = 0; kk < 4; kk++) {
            uint32_t am[2][4];
            #pragma unroll
            for (int m = 0; m < 2; m++) {
                const float* ar = Xs + (wm * 32 + m * 16) * PSTR + kk * 8;
                am[m][0] = tf32bits(ar[(g    ) * PSTR + qd    ]);
                am[m][1] = tf32bits(ar[(g + 8) * PSTR + qd    ]);
                am[m][2] = tf32bits(ar[(g    ) * PSTR + qd + 4]);
                am[m][3] = tf32bits(ar[(g + 8) * PSTR + qd + 4]);
            }
            #pragma unroll
            for (int nn = 0; nn < 8; nn++) {
                const float* br = Ws + (wn * 64 + nn * 8 + g) * PSTR + kk * 8;
                uint32_t b0 = tf32bits(br[qd]);
                uint32_t b1 = tf32bits(br[qd + 4]);
                mma_tf32(P.c[0][nn], am[0], b0, b1);
                mma_tf32(P.c[1][nn], am[1], b0, b1);
            }
        }
        __syncthreads();
    }
}

// grid (2, 128, 3)
__global__ void __launch_bounds__(256) proj_qkv(const float* __restrict__ x,
                                                const float* __restrict__ Wq,
                                                const float* __restrict__ Wk,
                                                const float* __restrict__ Wv)
{
    extern __shared__ float smp[];
    const float* W = (blockIdx.z == 0) ? Wq : (blockIdx.z == 1) ? Wk : Wv;
    float* dst     = (blockIdx.z == 0) ? g_q : (blockIdx.z == 1) ? g_k : g_v;
    const float sc = (blockIdx.z == 0) ? SCALE : 1.0f;
    const int m0 = blockIdx.y * 128, n0 = blockIdx.x * 128;

    ProjAcc P;
    proj_core(x, W, m0, n0, smp, P);

    const int lane = threadIdx.x & 31, warp = threadIdx.x >> 5;
    const int g = lane >> 2, qd = lane & 3;
    const int wm = warp >> 1, wn = warp & 1;

    #pragma unroll
    for (int m = 0; m < 2; m++)
        #pragma unroll
        for (int rr = 0; rr < 2; rr++) {
            int mg = m0 + wm * 32 + m * 16 + g + rr * 8;
            int b = mg >> 12, n = mg & (SEQ - 1);
            #pragma unroll
            for (int nn = 0; nn < 8; nn++) {
                int col = n0 + wn * 64 + nn * 8 + qd * 2;
                int h = col >> 6, d = col & 63;
                float v0 = tf32r(P.c[m][nn][rr * 2 + 0] * sc);
                float v1 = tf32r(P.c[m][nn][rr * 2 + 1] * sc);
                size_t bh = (size_t)(b * HEADS + h);
                if (blockIdx.z < 2) {
                    float* rowp = dst + (bh * SEQ + n) * HDIM;
                    rowp[dpack(d)]     = v0;
                    rowp[dpack(d + 1)] = v1;
                } else {
                    int jg = ((n >> 3) << 2) | (n & 3);
                    int comp = (n >> 2) & 1;
                    float* vp = dst + (bh * (SEQ / 2) + jg) * (HDIM * 2) + comp;
                    vp[d * 2]       = v0;
                    vp[(d + 1) * 2] = v1;
                }
            }
        }
}

// grid (2, 128)
__global__ void __launch_bounds__(256) proj_out(const float* __restrict__ Wp,
                                                const float* __restrict__ bp,
                                                float* __restrict__ out)
{
    extern __shared__ float smp[];
    const int m0 = blockIdx.y * 128, n0 = blockIdx.x * 128;

    ProjAcc P;
    proj_core(g_ao, Wp, m0, n0, smp, P);

    const int lane = threadIdx.x & 31, warp = threadIdx.x >> 5;
    const int g = lane >> 2, qd = lane & 3;
    const int wm = warp >> 1, wn = warp & 1;

    #pragma unroll
    for (int m = 0; m < 2; m++)
        #pragma unroll
        for (int rr = 0; rr < 2; rr++) {
            int mg = m0 + wm * 32 + m * 16 + g + rr * 8;
            #pragma unroll
            for (int nn = 0; nn < 8; nn++) {
                int col = n0 + wn * 64 + nn * 8 + qd * 2;
                float2 bb = *(const float2*)(bp + col);
                float2 v = make_float2(P.c[m][nn][rr * 2 + 0] + bb.x,
                                       P.c[m][nn][rr * 2 + 1] + bb.y);
                *(float2*)&out[(size_t)mg * CDIM + col] = v;
            }
        }
}

// ---------------------------------------------------------------------------
// tf32 mma.sync flash attention, pair-packed operands (LDS.64 fragments)
// grid = (SEQ/128, BH), block = 128, 2 CTAs/SM (no reg cap -> no spills)
// ---------------------------------------------------------------------------
__global__ void __launch_bounds__(128, 2) attn_mma()
{
    extern __shared__ float sm[];
    const int tid = threadIdx.x, lane = tid & 31, warp = tid >> 5;
    const int g = lane >> 2, qd = lane & 3;
    const int bh = blockIdx.y, q0 = blockIdx.x * 128;

    const float2* qg2 = (const float2*)(g_q + ((size_t)bh * SEQ + q0 + warp * 32) * HDIM);
    const float*  kg  = g_k + (size_t)bh * SEQ * HDIM;
    const float*  vgp = g_v + (size_t)bh * SEQ * HDIM;   // packed: 2048 rows x 128 floats

    uint32_t qf[2][8][4];
    #pragma unroll
    for (int m = 0; m < 2; m++)
        #pragma unroll
        for (int kk = 0; kk < 8; kk++) {
            float2 qa = qg2[(m * 16 + g    ) * 32 + kk * 4 + qd];
            float2 qb = qg2[(m * 16 + g + 8) * 32 + kk * 4 + qd];
            qf[m][kk][0] = __float_as_uint(qa.x);
            qf[m][kk][1] = __float_as_uint(qb.x);
            qf[m][kk][2] = __float_as_uint(qa.y);
            qf[m][kk][3] = __float_as_uint(qb.y);
        }

    float o[2][8][4] = {};
    float ls[4] = {0.f, 0.f, 0.f, 0.f};

    const uint32_t smb = smem_u32(sm);

    auto stage = [&](int t4, int buf) {
        uint32_t kdst = smb + buf * BUFBYTES;
        uint32_t vdst = kdst + KBYTES;
        int j0 = t4 * TK;
        #pragma unroll
        for (int i = 0; i < 8; i++) {
            int idx = i * 128 + tid;
            int r = idx >> 4, c = idx & 15;
            cpa16(kdst + (uint32_t)(r * KSTR + c * 4) * 4, kg + (size_t)(j0 + r) * 64 + c * 4);
            int r2 = idx >> 5, c2 = idx & 31;
            cpa16(vdst + (uint32_t)(r2 * (VSTR2 * 2) + c2 * 4) * 4,
                  vgp + (size_t)(j0 / 2 + r2) * 128 + c2 * 4);
        }
    };

    stage(0, 0);
    asm volatile("cp.async.commit_group;" ::: "memory");

    for (int t = 0; t < SEQ / TK; t++) {
        int buf = t & 1;
        if (t + 1 < SEQ / TK) {
            stage(t + 1, buf ^ 1);
            asm volatile("cp.async.commit_group;" ::: "memory");
            asm volatile("cp.async.wait_group 1;" ::: "memory");
        } else {
            asm volatile("cp.async.wait_group 0;" ::: "memory");
        }
        __syncthreads();

        const float*  Ks  = sm + buf * (BUFBYTES / 4);
        const float2* Vs2 = (const float2*)(Ks + KBYTES / 4);

        for (int nn = 0; nn < 8; nn++) {
            float c0[4] = {}, c1[4] = {};
            const float2* kb2 = (const float2*)Ks + (nn * 8 + g) * (KSTR / 2) + qd;
            #pragma unroll
            for (int kk = 0; kk < 8; kk++) {
                float2 b01 = kb2[kk * 4];
                uint32_t b0 = __float_as_uint(b01.x);
                uint32_t b1 = __float_as_uint(b01.y);
                mma_tf32(c0, qf[0][kk], b0, b1);
                mma_tf32(c1, qf[1][kk], b0, b1);
            }

            float e0[4], e1[4];
            #pragma unroll
            for (int i = 0; i < 4; i++) { e0[i] = __expf(c0[i]); e1[i] = __expf(c1[i]); }
            ls[0] += e0[0] + e0[1];  ls[1] += e0[2] + e0[3];
            ls[2] += e1[0] + e1[1];  ls[3] += e1[2] + e1[3];

            uint32_t pa0[4], pa1[4];
            permA(e0, pa0, lane);
            permA(e1, pa1, lane);

            const float2* vb2 = Vs2 + (nn * 4 + qd) * VSTR2 + g;
            #pragma unroll
            for (int dn = 0; dn < 8; dn++) {
                float2 v01 = vb2[dn * 8];
                uint32_t b0 = __float_as_uint(v01.x);
                uint32_t b1 = __float_as_uint(v01.y);
                mma_tf32(o[0][dn], pa0, b0, b1);
                mma_tf32(o[1][dn], pa1, b0, b1);
            }
        }
        __syncthreads();
    }

    #pragma unroll
    for (int i = 0; i < 4; i++) {
        ls[i] += __shfl_xor_sync(0xffffffffu, ls[i], 1);
        ls[i] += __shfl_xor_sync(0xffffffffu, ls[i], 2);
    }

    const int b = bh >> 2, h = bh & 3;
    #pragma unroll
    for (int m = 0; m < 2; m++)
        #pragma unroll
        for (int rr = 0; rr < 2; rr++) {
            int row = q0 + warp * 32 + m * 16 + g + rr * 8;
            float iv = 1.f / ls[m * 2 + rr];
            #pragma unroll
            for (int dn = 0; dn < 8; dn++) {
                float2 v = make_float2(tf32r(o[m][dn][rr * 2 + 0] * iv),
                                       tf32r(o[m][dn][rr * 2 + 1] * iv));
                *(float2*)&g_ao[((size_t)(b * SEQ) + row) * CDIM + h * 64 + dn * 8 + qd * 2] = v;
            }
        }
}

// ---------------------------------------------------------------------------
extern "C" void kernel_launch(void* const* d_in, const int* in_sizes, int n_in,
                              void* d_out, int out_size)
{
    (void)in_sizes; (void)n_in; (void)out_size;
    const float* x  = (const float*)d_in[0];
    const float* Wq = (const float*)d_in[1];
    const float* Wk = (const float*)d_in[2];
    const float* Wv = (const float*)d_in[3];
    const float* Wp = (const float*)d_in[4];
    const float* bp = (const float*)d_in[5];
    float* out = (float*)d_out;

    cudaFuncSetAttribute(proj_qkv, cudaFuncAttributeMaxDynamicSharedMemorySize, SMEM_PROJ);
    cudaFuncSetAttribute(proj_out, cudaFuncAttributeMaxDynamicSharedMemorySize, SMEM_PROJ);
    cudaFuncSetAttribute(attn_mma, cudaFuncAttributeMaxDynamicSharedMemorySize, SMEM_ATTN);

    dim3 gq(CDIM / 128, (BATCH * SEQ) / 128, 3);
    proj_qkv<<<gq, 256, SMEM_PROJ>>>(x, Wq, Wk, Wv);

    dim3 ga(SEQ / 128, BH);
    attn_mma<<<ga, 128, SMEM_ATTN>>>();

    dim3 go(CDIM / 128, (BATCH * SEQ) / 128);
    proj_out<<<go, 256, SMEM_PROJ>>>(Wp, bp, out);
}

// round 8
// speedup vs baseline: 1.4893x; 1.1820x over previous
#include <cuda_runtime.h>
#include <cuda_bf16.h>
#include <cstdint>

#define BATCH 4
#define SEQ   4096
#define CDIM  256
#define HEADS 4
#define HDIM  64
#define SCALE 0.125f
#define BH    (BATCH*HEADS)

// attention tiling
#define TK    64
#define KSTR  72                  // floats; 72 % 32 == 8 -> conflict-free LDS.64
#define VSTR2 68                  // float2; 68 % 16 == 4 -> conflict-free LDS.64
#define KBYTES (TK*KSTR*4)        // 18432
#define VBYTES ((TK/2)*VSTR2*8)   // 17408
#define BUFBYTES (KBYTES + VBYTES)
#define SMEM_ATTN (2*BUFBYTES)    // 71680 B

// projection GEMM tiling (tf32 mma): 128x128 tile, k-chunk 32
#define PSTR 36
#define PBUF (2*128*PSTR)
#define SMEM_PROJ (2*PBUF*4)      // 73728 B

// ---------------------------------------------------------------------------
// Scratch. q/k pair-packed along d: p(d) = (d&~7) | ((d&3)<<1) | ((d>>2)&1)
// v adjacent-pair packed along n: float2 row j = n>>1, component = n&1
//   -> PV k-slot qd reads kv pair (8nn+2qd, 8nn+2qd+1), matching the S
//      accumulator C-layout so exp(S) feeds the PV A-fragment by register
//      rename (no shuffles).
// ---------------------------------------------------------------------------
__device__ float g_q[BH * SEQ * HDIM];
__device__ float g_k[BH * SEQ * HDIM];
__device__ float g_v[BH * SEQ * HDIM];
__device__ float g_ao[BATCH * SEQ * CDIM];

// ---------------------------------------------------------------------------
__device__ __forceinline__ float tf32r(float x) {
    uint32_t u; asm("cvt.rna.tf32.f32 %0, %1;" : "=r"(u) : "f"(x));
    return __uint_as_float(u);
}
__device__ __forceinline__ uint32_t tf32bits(float x) {
    uint32_t u; asm("cvt.rna.tf32.f32 %0, %1;" : "=r"(u) : "f"(x));
    return u;
}
__device__ __forceinline__ uint32_t smem_u32(const void* p) {
    uint32_t a;
    asm("{ .reg .u64 t; cvta.to.shared.u64 t, %1; cvt.u32.u64 %0, t; }" : "=r"(a) : "l"(p));
    return a;
}
__device__ __forceinline__ void cpa16(uint32_t dst, const float* src) {
    asm volatile("cp.async.cg.shared.global [%0], [%1], 16;" :: "r"(dst), "l"(src) : "memory");
}
__device__ __forceinline__ void mma_tf32(float (&c)[4], const uint32_t (&a)[4],
                                         uint32_t b0, uint32_t b1) {
    asm("mma.sync.aligned.m16n8k8.row.col.f32.tf32.tf32.f32 "
        "{%0,%1,%2,%3}, {%4,%5,%6,%7}, {%8,%9}, {%0,%1,%2,%3};"
        : "+f"(c[0]), "+f"(c[1]), "+f"(c[2]), "+f"(c[3])
        : "r"(a[0]), "r"(a[1]), "r"(a[2]), "r"(a[3]), "r"(b0), "r"(b1));
}
__device__ __forceinline__ int dpack(int d) {
    return (d & ~7) | ((d & 3) << 1) | ((d >> 2) & 1);
}

// ---------------------------------------------------------------------------
// tf32 mma projection core
// ---------------------------------------------------------------------------
struct ProjAcc { float c[2][8][4]; };

__device__ __forceinline__ void proj_core(const float* __restrict__ A,
                                          const float* __restrict__ Bm,
                                          int m0, int n0, float* smp, ProjAcc& P)
{
    const int tid = threadIdx.x, lane = tid & 31, warp = tid >> 5;
    const int g = lane >> 2, qd = lane & 3;
    const int wm = warp >> 1, wn = warp & 1;
    const uint32_t smb = smem_u32(smp);

    #pragma unroll
    for (int m = 0; m < 2; m++)
        #pragma unroll
        for (int nn = 0; nn < 8; nn++)
            #pragma unroll
            for (int i = 0; i < 4; i++) P.c[m][nn][i] = 0.f;

    auto stage = [&](int kc, int b) {
        uint32_t xb = smb + (uint32_t)(b * PBUF) * 4;
        uint32_t wb = xb + (uint32_t)(128 * PSTR) * 4;
        int k0 = kc * 32;
        #pragma unroll
        for (int p = 0; p < 4; p++) {
            int idx = p * 256 + tid;
            int r = idx >> 3, cc = idx & 7;
            cpa16(xb + (uint32_t)(r * PSTR + cc * 4) * 4, A  + (size_t)(m0 + r) * CDIM + k0 + cc * 4);
            cpa16(wb + (uint32_t)(r * PSTR + cc * 4) * 4, Bm + (size_t)(n0 + r) * CDIM + k0 + cc * 4);
        }
    };

    stage(0, 0);
    asm volatile("cp.async.commit_group;" ::: "memory");

    for (int kc = 0; kc < CDIM / 32; kc++) {
        int b = kc & 1;
        if (kc + 1 < CDIM / 32) {
            stage(kc + 1, b ^ 1);
            asm volatile("cp.async.commit_group;" ::: "memory");
            asm volatile("cp.async.wait_group 1;" ::: "memory");
        } else {
            asm volatile("cp.async.wait_group 0;" ::: "memory");
        }
        __syncthreads();

        const float* Xs = smp + b * PBUF;
        const float* Ws = Xs + 128 * PSTR;

        #pragma unroll
        for (int kk = 0; kk < 4; kk++) {
            uint32_t am[2][4];
            #pragma unroll
            for (int m = 0; m < 2; m++) {
                const float* ar = Xs + (wm * 32 + m * 16) * PSTR + kk * 8;
                am[m][0] = tf32bits(ar[(g    ) * PSTR + qd    ]);
                am[m][1] = tf32bits(ar[(g + 8) * PSTR + qd    ]);
                am[m][2] = tf32bits(ar[(g    ) * PSTR + qd + 4]);
                am[m][3] = tf32bits(ar[(g + 8) * PSTR + qd + 4]);
            }
            #pragma unroll
            for (int nn = 0; nn < 8; nn++) {
                const float* br = Ws + (wn * 64 + nn * 8 + g) * PSTR + kk * 8;
                uint32_t b0 = tf32bits(br[qd]);
                uint32_t b1 = tf32bits(br[qd + 4]);
                mma_tf32(P.c[0][nn], am[0], b0, b1);
                mma_tf32(P.c[1][nn], am[1], b0, b1);
            }
        }
        __syncthreads();
    }
}

// grid (2, 128, 3)
__global__ void __launch_bounds__(256) proj_qkv(const float* __restrict__ x,
                                                const float* __restrict__ Wq,
                                                const float* __restrict__ Wk,
                                                const float* __restrict__ Wv)
{
    extern __shared__ float smp[];
    const float* W = (blockIdx.z == 0) ? Wq : (blockIdx.z == 1) ? Wk : Wv;
    float* dst     = (blockIdx.z == 0) ? g_q : (blockIdx.z == 1) ? g_k : g_v;
    const float sc = (blockIdx.z == 0) ? SCALE : 1.0f;
    const int m0 = blockIdx.y * 128, n0 = blockIdx.x * 128;

    ProjAcc P;
    proj_core(x, W, m0, n0, smp, P);

    const int lane = threadIdx.x & 31, warp = threadIdx.x >> 5;
    const int g = lane >> 2, qd = lane & 3;
    const int wm = warp >> 1, wn = warp & 1;

    #pragma unroll
    for (int m = 0; m < 2; m++)
        #pragma unroll
        for (int rr = 0; rr < 2; rr++) {
            int mg = m0 + wm * 32 + m * 16 + g + rr * 8;
            int b = mg >> 12, n = mg & (SEQ - 1);
            #pragma unroll
            for (int nn = 0; nn < 8; nn++) {
                int col = n0 + wn * 64 + nn * 8 + qd * 2;
                int h = col >> 6, d = col & 63;
                float v0 = tf32r(P.c[m][nn][rr * 2 + 0] * sc);
                float v1 = tf32r(P.c[m][nn][rr * 2 + 1] * sc);
                size_t bh = (size_t)(b * HEADS + h);
                if (blockIdx.z < 2) {
                    float* rowp = dst + (bh * SEQ + n) * HDIM;
                    rowp[dpack(d)]     = v0;
                    rowp[dpack(d + 1)] = v1;
                } else {
                    // V: adjacent-pair packed along n (float2 row n>>1, comp n&1)
                    float* vp = dst + (bh * (SEQ / 2) + (n >> 1)) * (HDIM * 2) + (n & 1);
                    vp[d * 2]       = v0;
                    vp[(d + 1) * 2] = v1;
                }
            }
        }
}

// grid (2, 128)
__global__ void __launch_bounds__(256) proj_out(const float* __restrict__ Wp,
                                                const float* __restrict__ bp,
                                                float* __restrict__ out)
{
    extern __shared__ float smp[];
    const int m0 = blockIdx.y * 128, n0 = blockIdx.x * 128;

    ProjAcc P;
    proj_core(g_ao, Wp, m0, n0, smp, P);

    const int lane = threadIdx.x & 31, warp = threadIdx.x >> 5;
    const int g = lane >> 2, qd = lane & 3;
    const int wm = warp >> 1, wn = warp & 1;

    #pragma unroll
    for (int m = 0; m < 2; m++)
        #pragma unroll
        for (int rr = 0; rr < 2; rr++) {
            int mg = m0 + wm * 32 + m * 16 + g + rr * 8;
            #pragma unroll
            for (int nn = 0; nn < 8; nn++) {
                int col = n0 + wn * 64 + nn * 8 + qd * 2;
                float2 bb = *(const float2*)(bp + col);
                float2 v = make_float2(P.c[m][nn][rr * 2 + 0] + bb.x,
                                       P.c[m][nn][rr * 2 + 1] + bb.y);
                *(float2*)&out[(size_t)mg * CDIM + col] = v;
            }
        }
}

// ---------------------------------------------------------------------------
// tf32 mma.sync flash attention: pair-packed LDS.64 operands, shuffle-free
// P feed (register rename via V row permutation), split S chains.
// grid = (SEQ/128, BH), block = 128, 2 CTAs/SM
// ---------------------------------------------------------------------------
__global__ void __launch_bounds__(128, 2) attn_mma()
{
    extern __shared__ float sm[];
    const int tid = threadIdx.x, lane = tid & 31, warp = tid >> 5;
    const int g = lane >> 2, qd = lane & 3;
    const int bh = blockIdx.y, q0 = blockIdx.x * 128;

    const float2* qg2 = (const float2*)(g_q + ((size_t)bh * SEQ + q0 + warp * 32) * HDIM);
    const float*  kg  = g_k + (size_t)bh * SEQ * HDIM;
    const float*  vgp = g_v + (size_t)bh * SEQ * HDIM;   // packed: 2048 float2-rows x 64

    uint32_t qf[2][8][4];
    #pragma unroll
    for (int m = 0; m < 2; m++)
        #pragma unroll
        for (int kk = 0; kk < 8; kk++) {
            float2 qa = qg2[(m * 16 + g    ) * 32 + kk * 4 + qd];
            float2 qb = qg2[(m * 16 + g + 8) * 32 + kk * 4 + qd];
            qf[m][kk][0] = __float_as_uint(qa.x);
            qf[m][kk][1] = __float_as_uint(qb.x);
            qf[m][kk][2] = __float_as_uint(qa.y);
            qf[m][kk][3] = __float_as_uint(qb.y);
        }

    float o[2][8][4] = {};
    float ls[4] = {0.f, 0.f, 0.f, 0.f};

    const uint32_t smb = smem_u32(sm);

    auto stage = [&](int t4, int buf) {
        uint32_t kdst = smb + buf * BUFBYTES;
        uint32_t vdst = kdst + KBYTES;
        int j0 = t4 * TK;
        #pragma unroll
        for (int i = 0; i < 8; i++) {
            int idx = i * 128 + tid;
            int r = idx >> 4, c = idx & 15;
            cpa16(kdst + (uint32_t)(r * KSTR + c * 4) * 4, kg + (size_t)(j0 + r) * 64 + c * 4);
            int r2 = idx >> 5, c2 = idx & 31;
            cpa16(vdst + (uint32_t)(r2 * (VSTR2 * 2) + c2 * 4) * 4,
                  vgp + (size_t)(j0 / 2 + r2) * 128 + c2 * 4);
        }
    };

    stage(0, 0);
    asm volatile("cp.async.commit_group;" ::: "memory");

    for (int t = 0; t < SEQ / TK; t++) {
        int buf = t & 1;
        if (t + 1 < SEQ / TK) {
            stage(t + 1, buf ^ 1);
            asm volatile("cp.async.commit_group;" ::: "memory");
            asm volatile("cp.async.wait_group 1;" ::: "memory");
        } else {
            asm volatile("cp.async.wait_group 0;" ::: "memory");
        }
        __syncthreads();

        const float*  Ks  = sm + buf * (BUFBYTES / 4);
        const float2* Vs2 = (const float2*)(Ks + KBYTES / 4);

        #pragma unroll
        for (int nn = 0; nn < 8; nn++) {
            // ---- S = Q K^T (two 4-deep chains per accumulator) ----
            float c0a[4] = {}, c0b[4] = {}, c1a[4] = {}, c1b[4] = {};
            const float2* kb2 = (const float2*)Ks + (nn * 8 + g) * (KSTR / 2) + qd;
            #pragma unroll
            for (int kk = 0; kk < 4; kk++) {
                float2 b01 = kb2[kk * 4];
                uint32_t b0 = __float_as_uint(b01.x);
                uint32_t b1 = __float_as_uint(b01.y);
                mma_tf32(c0a, qf[0][kk], b0, b1);
                mma_tf32(c1a, qf[1][kk], b0, b1);
            }
            #pragma unroll
            for (int kk = 4; kk < 8; kk++) {
                float2 b01 = kb2[kk * 4];
                uint32_t b0 = __float_as_uint(b01.x);
                uint32_t b1 = __float_as_uint(b01.y);
                mma_tf32(c0b, qf[0][kk], b0, b1);
                mma_tf32(c1b, qf[1][kk], b0, b1);
            }

            // ---- exp + row-sum ----
            float e0[4], e1[4];
            #pragma unroll
            for (int i = 0; i < 4; i++) {
                e0[i] = __expf(c0a[i] + c0b[i]);
                e1[i] = __expf(c1a[i] + c1b[i]);
            }
            ls[0] += e0[0] + e0[1];  ls[1] += e0[2] + e0[3];
            ls[2] += e1[0] + e1[1];  ls[3] += e1[2] + e1[3];

            // ---- PV A-fragment = register rename of C-fragment ----
            // (V rows permuted so k-slot qd <-> kv 2qd, slot qd+4 <-> kv 2qd+1)
            uint32_t pa0[4], pa1[4];
            pa0[0] = tf32bits(e0[0]); pa0[1] = tf32bits(e0[2]);
            pa0[2] = tf32bits(e0[1]); pa0[3] = tf32bits(e0[3]);
            pa1[0] = tf32bits(e1[0]); pa1[1] = tf32bits(e1[2]);
            pa1[2] = tf32bits(e1[1]); pa1[3] = tf32bits(e1[3]);

            // ---- O += P V ----
            const float2* vb2 = Vs2 + (nn * 4 + qd) * VSTR2 + g;
            #pragma unroll
            for (int dn = 0; dn < 8; dn++) {
                float2 v01 = vb2[dn * 8];
                uint32_t b0 = __float_as_uint(v01.x);
                uint32_t b1 = __float_as_uint(v01.y);
                mma_tf32(o[0][dn], pa0, b0, b1);
                mma_tf32(o[1][dn], pa1, b0, b1);
            }
        }
        __syncthreads();
    }

    #pragma unroll
    for (int i = 0; i < 4; i++) {
        ls[i] += __shfl_xor_sync(0xffffffffu, ls[i], 1);
        ls[i] += __shfl_xor_sync(0xffffffffu, ls[i], 2);
    }

    const int b = bh >> 2, h = bh & 3;
    #pragma unroll
    for (int m = 0; m < 2; m++)
        #pragma unroll
        for (int rr = 0; rr < 2; rr++) {
            int row = q0 + warp * 32 + m * 16 + g + rr * 8;
            float iv = 1.f / ls[m * 2 + rr];
            #pragma unroll
            for (int dn = 0; dn < 8; dn++) {
                float2 v = make_float2(tf32r(o[m][dn][rr * 2 + 0] * iv),
                                       tf32r(o[m][dn][rr * 2 + 1] * iv));
                *(float2*)&g_ao[((size_t)(b * SEQ) + row) * CDIM + h * 64 + dn * 8 + qd * 2] = v;
            }
        }
}

// ---------------------------------------------------------------------------
extern "C" void kernel_launch(void* const* d_in, const int* in_sizes, int n_in,
                              void* d_out, int out_size)
{
    (void)in_sizes; (void)n_in; (void)out_size;
    const float* x  = (const float*)d_in[0];
    const float* Wq = (const float*)d_in[1];
    const float* Wk = (const float*)d_in[2];
    const float* Wv = (const float*)d_in[3];
    const float* Wp = (const float*)d_in[4];
    const float* bp = (const float*)d_in[5];
    float* out = (float*)d_out;

    cudaFuncSetAttribute(proj_qkv, cudaFuncAttributeMaxDynamicSharedMemorySize, SMEM_PROJ);
    cudaFuncSetAttribute(proj_out, cudaFuncAttributeMaxDynamicSharedMemorySize, SMEM_PROJ);
    cudaFuncSetAttribute(attn_mma, cudaFuncAttributeMaxDynamicSharedMemorySize, SMEM_ATTN);

    dim3 gq(CDIM / 128, (BATCH * SEQ) / 128, 3);
    proj_qkv<<<gq, 256, SMEM_PROJ>>>(x, Wq, Wk, Wv);

    dim3 ga(SEQ / 128, BH);
    attn_mma<<<ga, 128, SMEM_ATTN>>>();

    dim3 go(CDIM / 128, (BATCH * SEQ) / 128);
    proj_out<<<go, 256, SMEM_PROJ>>>(Wp, bp, out);
}

// round 9
// speedup vs baseline: 1.4907x; 1.0009x over previous
#include <cuda_runtime.h>
#include <cuda_bf16.h>
#include <cstdint>

#define BATCH 4
#define SEQ   4096
#define CDIM  256
#define HEADS 4
#define HDIM  64
#define SCALE 0.125f
#define BH    (BATCH*HEADS)

// attention tiling
#define TK    64
#define KSTR  72                  // floats; conflict-free LDS.64
#define VSTR2 68                  // float2; conflict-free LDS.64
#define KBYTES (TK*KSTR*4)
#define VBYTES ((TK/2)*VSTR2*8)
#define BUFBYTES (KBYTES + VBYTES)
#define SMEM_ATTN (2*BUFBYTES)    // 71680 B

// projection GEMM tiling: 128x128 tile, k-chunk 32, packed tf32 operands
#define PSTR2 20                  // float2 row stride; 4g+qd distinct mod 16 -> conflict-free
#define PBUF (2*128*PSTR2*2)      // floats per buffer (X + W tiles)
#define SMEM_PROJ (2*PBUF*4)      // 81920 B

#define XGROUPS (BATCH*SEQ*CDIM/8)   // 524288
#define WGROUPS (CDIM*CDIM/8)        // 8192
#define PACKTOT (XGROUPS + 4*WGROUPS)

// ---------------------------------------------------------------------------
// Scratch. All attention/projection operands tf32-rounded + K-pair-packed:
// per 8-group [d0..d7] stored as [d0,d4,d1,d5,d2,d6,d3,d7].
// v adjacent-pair packed along n: float2 row n>>1, component n&1.
// ---------------------------------------------------------------------------
__device__ float g_q[BH * SEQ * HDIM];
__device__ float g_k[BH * SEQ * HDIM];
__device__ float g_v[BH * SEQ * HDIM];
__device__ float g_ao[BATCH * SEQ * CDIM];     // pair-packed along CDIM
__device__ float g_xp[BATCH * SEQ * CDIM];     // packed x
__device__ float g_wp[4 * CDIM * CDIM];        // packed Wq,Wk,Wv,Wp

// ---------------------------------------------------------------------------
__device__ __forceinline__ float tf32r(float x) {
    uint32_t u; asm("cvt.rna.tf32.f32 %0, %1;" : "=r"(u) : "f"(x));
    return __uint_as_float(u);
}
__device__ __forceinline__ uint32_t smem_u32(const void* p) {
    uint32_t a;
    asm("{ .reg .u64 t; cvta.to.shared.u64 t, %1; cvt.u32.u64 %0, t; }" : "=r"(a) : "l"(p));
    return a;
}
__device__ __forceinline__ void cpa16(uint32_t dst, const float* src) {
    asm volatile("cp.async.cg.shared.global [%0], [%1], 16;" :: "r"(dst), "l"(src) : "memory");
}
__device__ __forceinline__ void mma_tf32(float (&c)[4], const uint32_t (&a)[4],
                                         uint32_t b0, uint32_t b1) {
    asm("mma.sync.aligned.m16n8k8.row.col.f32.tf32.tf32.f32 "
        "{%0,%1,%2,%3}, {%4,%5,%6,%7}, {%8,%9}, {%0,%1,%2,%3};"
        : "+f"(c[0]), "+f"(c[1]), "+f"(c[2]), "+f"(c[3])
        : "r"(a[0]), "r"(a[1]), "r"(a[2]), "r"(a[3]), "r"(b0), "r"(b1));
}
__device__ __forceinline__ int dpack(int d) {
    return (d & ~7) | ((d & 3) << 1) | ((d >> 2) & 1);
}

// ---------------------------------------------------------------------------
// Prepass: tf32-round + pair-pack x and the four weight matrices.
// Each thread handles one 8-group (32B in, 32B out).
// ---------------------------------------------------------------------------
__global__ void pack_tf32(const float* __restrict__ x,
                          const float* __restrict__ Wq,
                          const float* __restrict__ Wk,
                          const float* __restrict__ Wv,
                          const float* __restrict__ Wp)
{
    int i = blockIdx.x * 256 + threadIdx.x;
    if (i >= PACKTOT) return;
    const float* src;
    float* dst;
    if (i < XGROUPS) {
        src = x; dst = g_xp;
    } else {
        int j = i - XGROUPS;
        int w = j >> 13;
        i = j & (WGROUPS - 1);
        src = (w == 0) ? Wq : (w == 1) ? Wk : (w == 2) ? Wv : Wp;
        dst = g_wp + w * (CDIM * CDIM);
    }
    float4 a = ((const float4*)src)[i * 2];
    float4 b = ((const float4*)src)[i * 2 + 1];
    float4 o0 = make_float4(tf32r(a.x), tf32r(b.x), tf32r(a.y), tf32r(b.y));
    float4 o1 = make_float4(tf32r(a.z), tf32r(b.z), tf32r(a.w), tf32r(b.w));
    ((float4*)dst)[i * 2]     = o0;
    ((float4*)dst)[i * 2 + 1] = o1;
}

// ---------------------------------------------------------------------------
// tf32 mma projection core on PACKED operands: zero cvt, all-LDS.64 fragments
// ---------------------------------------------------------------------------
struct ProjAcc { float c[2][8][4]; };

__device__ __forceinline__ void proj_core(const float* __restrict__ A,
                                          const float* __restrict__ Bm,
                                          int m0, int n0, float* smp, ProjAcc& P)
{
    const int tid = threadIdx.x, lane = tid & 31, warp = tid >> 5;
    const int g = lane >> 2, qd = lane & 3;
    const int wm = warp >> 1, wn = warp & 1;
    const uint32_t smb = smem_u32(smp);

    #pragma unroll
    for (int m = 0; m < 2; m++)
        #pragma unroll
        for (int nn = 0; nn < 8; nn++)
            #pragma unroll
            for (int i = 0; i < 4; i++) P.c[m][nn][i] = 0.f;

    auto stage = [&](int kc, int b) {
        uint32_t xb = smb + (uint32_t)(b * PBUF) * 4;
        uint32_t wb = xb + (uint32_t)(128 * PSTR2 * 2) * 4;
        int k0 = kc * 32;
        #pragma unroll
        for (int p = 0; p < 4; p++) {
            int idx = p * 256 + tid;
            int r = idx >> 3, cc = idx & 7;
            cpa16(xb + (uint32_t)(r * (PSTR2 * 2) + cc * 4) * 4,
                  A  + (size_t)(m0 + r) * CDIM + k0 + cc * 4);
            cpa16(wb + (uint32_t)(r * (PSTR2 * 2) + cc * 4) * 4,
                  Bm + (size_t)(n0 + r) * CDIM + k0 + cc * 4);
        }
    };

    stage(0, 0);
    asm volatile("cp.async.commit_group;" ::: "memory");

    for (int kc = 0; kc < CDIM / 32; kc++) {
        int b = kc & 1;
        if (kc + 1 < CDIM / 32) {
            stage(kc + 1, b ^ 1);
            asm volatile("cp.async.commit_group;" ::: "memory");
            asm volatile("cp.async.wait_group 1;" ::: "memory");
        } else {
            asm volatile("cp.async.wait_group 0;" ::: "memory");
        }
        __syncthreads();

        const float2* Xs2 = (const float2*)(smp + b * PBUF);
        const float2* Ws2 = Xs2 + 128 * PSTR2;

        #pragma unroll
        for (int kk = 0; kk < 4; kk++) {
            uint32_t am[2][4];
            #pragma unroll
            for (int m = 0; m < 2; m++) {
                int r0 = wm * 32 + m * 16;
                float2 qa = Xs2[(r0 + g    ) * PSTR2 + kk * 4 + qd];
                float2 qb = Xs2[(r0 + g + 8) * PSTR2 + kk * 4 + qd];
                am[m][0] = __float_as_uint(qa.x);
                am[m][1] = __float_as_uint(qb.x);
                am[m][2] = __float_as_uint(qa.y);
                am[m][3] = __float_as_uint(qb.y);
            }
            #pragma unroll
            for (int nn = 0; nn < 8; nn++) {
                float2 bb = Ws2[(wn * 64 + nn * 8 + g) * PSTR2 + kk * 4 + qd];
                uint32_t b0 = __float_as_uint(bb.x);
                uint32_t b1 = __float_as_uint(bb.y);
                mma_tf32(P.c[0][nn], am[0], b0, b1);
                mma_tf32(P.c[1][nn], am[1], b0, b1);
            }
        }
        __syncthreads();
    }
}

// grid (2, 128, 3)
__global__ void __launch_bounds__(256) proj_qkv()
{
    extern __shared__ float smp[];
    const int z = blockIdx.z;
    const float* W = g_wp + z * (CDIM * CDIM);
    float* dst     = (z == 0) ? g_q : (z == 1) ? g_k : g_v;
    const float sc = (z == 0) ? SCALE : 1.0f;
    const int m0 = blockIdx.y * 128, n0 = blockIdx.x * 128;

    ProjAcc P;
    proj_core(g_xp, W, m0, n0, smp, P);

    const int lane = threadIdx.x & 31, warp = threadIdx.x >> 5;
    const int g = lane >> 2, qd = lane & 3;
    const int wm = warp >> 1, wn = warp & 1;

    #pragma unroll
    for (int m = 0; m < 2; m++)
        #pragma unroll
        for (int rr = 0; rr < 2; rr++) {
            int mg = m0 + wm * 32 + m * 16 + g + rr * 8;
            int b = mg >> 12, n = mg & (SEQ - 1);
            #pragma unroll
            for (int nn = 0; nn < 8; nn++) {
                int col = n0 + wn * 64 + nn * 8 + qd * 2;
                int h = col >> 6, d = col & 63;
                float v0 = tf32r(P.c[m][nn][rr * 2 + 0] * sc);
                float v1 = tf32r(P.c[m][nn][rr * 2 + 1] * sc);
                size_t bh = (size_t)(b * HEADS + h);
                if (z < 2) {
                    float* rowp = dst + (bh * SEQ + n) * HDIM;
                    rowp[dpack(d)]     = v0;
                    rowp[dpack(d + 1)] = v1;
                } else {
                    float* vp = dst + (bh * (SEQ / 2) + (n >> 1)) * (HDIM * 2) + (n & 1);
                    vp[d * 2]       = v0;
                    vp[(d + 1) * 2] = v1;
                }
            }
        }
}

// grid (2, 128): out = ao @ Wp^T + bp   (A = g_ao, packed along CDIM)
__global__ void __launch_bounds__(256) proj_out(const float* __restrict__ bp,
                                                float* __restrict__ out)
{
    extern __shared__ float smp[];
    const int m0 = blockIdx.y * 128, n0 = blockIdx.x * 128;

    ProjAcc P;
    proj_core(g_ao, g_wp + 3 * (CDIM * CDIM), m0, n0, smp, P);

    const int lane = threadIdx.x & 31, warp = threadIdx.x >> 5;
    const int g = lane >> 2, qd = lane & 3;
    const int wm = warp >> 1, wn = warp & 1;

    #pragma unroll
    for (int m = 0; m < 2; m++)
        #pragma unroll
        for (int rr = 0; rr < 2; rr++) {
            int mg = m0 + wm * 32 + m * 16 + g + rr * 8;
            #pragma unroll
            for (int nn = 0; nn < 8; nn++) {
                int col = n0 + wn * 64 + nn * 8 + qd * 2;
                float2 bb = *(const float2*)(bp + col);
                float2 v = make_float2(P.c[m][nn][rr * 2 + 0] + bb.x,
                                       P.c[m][nn][rr * 2 + 1] + bb.y);
                *(float2*)&out[(size_t)mg * CDIM + col] = v;
            }
        }
}

// ---------------------------------------------------------------------------
// tf32 mma.sync flash attention (identical to R8 except packed g_ao epilogue)
// grid = (SEQ/128, BH), block = 128, 2 CTAs/SM
// ---------------------------------------------------------------------------
__global__ void __launch_bounds__(128, 2) attn_mma()
{
    extern __shared__ float sm[];
    const int tid = threadIdx.x, lane = tid & 31, warp = tid >> 5;
    const int g = lane >> 2, qd = lane & 3;
    const int bh = blockIdx.y, q0 = blockIdx.x * 128;

    const float2* qg2 = (const float2*)(g_q + ((size_t)bh * SEQ + q0 + warp * 32) * HDIM);
    const float*  kg  = g_k + (size_t)bh * SEQ * HDIM;
    const float*  vgp = g_v + (size_t)bh * SEQ * HDIM;

    uint32_t qf[2][8][4];
    #pragma unroll
    for (int m = 0; m < 2; m++)
        #pragma unroll
        for (int kk = 0; kk < 8; kk++) {
            float2 qa = qg2[(m * 16 + g    ) * 32 + kk * 4 + qd];
            float2 qb = qg2[(m * 16 + g + 8) * 32 + kk * 4 + qd];
            qf[m][kk][0] = __float_as_uint(qa.x);
            qf[m][kk][1] = __float_as_uint(qb.x);
            qf[m][kk][2] = __float_as_uint(qa.y);
            qf[m][kk][3] = __float_as_uint(qb.y);
        }

    float o[2][8][4] = {};
    float ls[4] = {0.f, 0.f, 0.f, 0.f};

    const uint32_t smb = smem_u32(sm);

    auto stage = [&](int t4, int buf) {
        uint32_t kdst = smb + buf * BUFBYTES;
        uint32_t vdst = kdst + KBYTES;
        int j0 = t4 * TK;
        #pragma unroll
        for (int i = 0; i < 8; i++) {
            int idx = i * 128 + tid;
            int r = idx >> 4, c = idx & 15;
            cpa16(kdst + (uint32_t)(r * KSTR + c * 4) * 4, kg + (size_t)(j0 + r) * 64 + c * 4);
            int r2 = idx >> 5, c2 = idx & 31;
            cpa16(vdst + (uint32_t)(r2 * (VSTR2 * 2) + c2 * 4) * 4,
                  vgp + (size_t)(j0 / 2 + r2) * 128 + c2 * 4);
        }
    };

    stage(0, 0);
    asm volatile("cp.async.commit_group;" ::: "memory");

    for (int t = 0; t < SEQ / TK; t++) {
        int buf = t & 1;
        if (t + 1 < SEQ / TK) {
            stage(t + 1, buf ^ 1);
            asm volatile("cp.async.commit_group;" ::: "memory");
            asm volatile("cp.async.wait_group 1;" ::: "memory");
        } else {
            asm volatile("cp.async.wait_group 0;" ::: "memory");
        }
        __syncthreads();

        const float*  Ks  = sm + buf * (BUFBYTES / 4);
        const float2* Vs2 = (const float2*)(Ks + KBYTES / 4);

        #pragma unroll
        for (int nn = 0; nn < 8; nn++) {
            float c0a[4] = {}, c0b[4] = {}, c1a[4] = {}, c1b[4] = {};
            const float2* kb2 = (const float2*)Ks + (nn * 8 + g) * (KSTR / 2) + qd;
            #pragma unroll
            for (int kk = 0; kk < 4; kk++) {
                float2 b01 = kb2[kk * 4];
                uint32_t b0 = __float_as_uint(b01.x);
                uint32_t b1 = __float_as_uint(b01.y);
                mma_tf32(c0a, qf[0][kk], b0, b1);
                mma_tf32(c1a, qf[1][kk], b0, b1);
            }
            #pragma unroll
            for (int kk = 4; kk < 8; kk++) {
                float2 b01 = kb2[kk * 4];
                uint32_t b0 = __float_as_uint(b01.x);
                uint32_t b1 = __float_as_uint(b01.y);
                mma_tf32(c0b, qf[0][kk], b0, b1);
                mma_tf32(c1b, qf[1][kk], b0, b1);
            }

            float e0[4], e1[4];
            #pragma unroll
            for (int i = 0; i < 4; i++) {
                e0[i] = __expf(c0a[i] + c0b[i]);
                e1[i] = __expf(c1a[i] + c1b[i]);
            }
            ls[0] += e0[0] + e0[1];  ls[1] += e0[2] + e0[3];
            ls[2] += e1[0] + e1[1];  ls[3] += e1[2] + e1[3];

            uint32_t pa0[4], pa1[4];
            pa0[0] = __float_as_uint(e0[0]); pa0[1] = __float_as_uint(e0[2]);
            pa0[2] = __float_as_uint(e0[1]); pa0[3] = __float_as_uint(e0[3]);
            pa1[0] = __float_as_uint(e1[0]); pa1[1] = __float_as_uint(e1[2]);
            pa1[2] = __float_as_uint(e1[1]); pa1[3] = __float_as_uint(e1[3]);

            const float2* vb2 = Vs2 + (nn * 4 + qd) * VSTR2 + g;
            #pragma unroll
            for (int dn = 0; dn < 8; dn++) {
                float2 v01 = vb2[dn * 8];
                uint32_t b0 = __float_as_uint(v01.x);
                uint32_t b1 = __float_as_uint(v01.y);
                mma_tf32(o[0][dn], pa0, b0, b1);
                mma_tf32(o[1][dn], pa1, b0, b1);
            }
        }
        __syncthreads();
    }

    #pragma unroll
    for (int i = 0; i < 4; i++) {
        ls[i] += __shfl_xor_sync(0xffffffffu, ls[i], 1);
        ls[i] += __shfl_xor_sync(0xffffffffu, ls[i], 2);
    }

    const int b = bh >> 2, h = bh & 3;
    #pragma unroll
    for (int m = 0; m < 2; m++)
        #pragma unroll
        for (int rr = 0; rr < 2; rr++) {
            int row = q0 + warp * 32 + m * 16 + g + rr * 8;
            float iv = 1.f / ls[m * 2 + rr];
            float* aop = g_ao + ((size_t)(b * SEQ) + row) * CDIM + h * 64;
            #pragma unroll
            for (int dn = 0; dn < 8; dn++) {
                int d = dn * 8 + qd * 2;
                aop[(dn * 8) + dpack(d & 7)]       = tf32r(o[m][dn][rr * 2 + 0] * iv);
                aop[(dn * 8) + dpack((d + 1) & 7)] = tf32r(o[m][dn][rr * 2 + 1] * iv);
            }
        }
}

// ---------------------------------------------------------------------------
extern "C" void kernel_launch(void* const* d_in, const int* in_sizes, int n_in,
                              void* d_out, int out_size)
{
    (void)in_sizes; (void)n_in; (void)out_size;
    const float* x  = (const float*)d_in[0];
    const float* Wq = (const float*)d_in[1];
    const float* Wk = (const float*)d_in[2];
    const float* Wv = (const float*)d_in[3];
    const float* Wp = (const float*)d_in[4];
    const float* bp = (const float*)d_in[5];
    float* out = (float*)d_out;

    cudaFuncSetAttribute(proj_qkv, cudaFuncAttributeMaxDynamicSharedMemorySize, SMEM_PROJ);
    cudaFuncSetAttribute(proj_out, cudaFuncAttributeMaxDynamicSharedMemorySize, SMEM_PROJ);
    cudaFuncSetAttribute(attn_mma, cudaFuncAttributeMaxDynamicSharedMemorySize, SMEM_ATTN);

    pack_tf32<<<(PACKTOT + 255) / 256, 256>>>(x, Wq, Wk, Wv, Wp);

    dim3 gq(CDIM / 128, (BATCH * SEQ) / 128, 3);
    proj_qkv<<<gq, 256, SMEM_PROJ>>>();

    dim3 ga(SEQ / 128, BH);
    attn_mma<<<ga, 128, SMEM_ATTN>>>();

    dim3 go(CDIM / 128, (BATCH * SEQ) / 128);
    proj_out<<<go, 256, SMEM_PROJ>>>(bp, out);
}

// round 10
// speedup vs baseline: 1.5647x; 1.0497x over previous
#include <cuda_runtime.h>
#include <cuda_bf16.h>
#include <cstdint>

#define BATCH 4
#define SEQ   4096
#define CDIM  256
#define HEADS 4
#define HDIM  64
#define SCALE 0.125f
#define LOG2E 1.44269504f
#define BH    (BATCH*HEADS)

// attention tiling
#define TK    64
#define KSTR  72                  // floats; conflict-free LDS.64
#define VSTR2 68                  // float2; conflict-free LDS.64
#define KBYTES (TK*KSTR*4)
#define VBYTES ((TK/2)*VSTR2*8)
#define BUFBYTES (KBYTES + VBYTES)
#define NBUF 3
#define SMEM_ATTN (NBUF*BUFBYTES)   // 107520 B (2 CTAs/SM: 215KB < 228KB)
#define NT (SEQ/TK)                 // 64 tiles

// projection GEMM tiling: 128x128 tile, k-chunk 32, packed tf32 operands
#define PSTR2 20
#define PBUF (2*128*PSTR2*2)
#define SMEM_PROJ (2*PBUF*4)      // 81920 B

#define XGROUPS (BATCH*SEQ*CDIM/8)
#define WGROUPS (CDIM*CDIM/8)
#define PACKTOT (XGROUPS + 4*WGROUPS)

// ---------------------------------------------------------------------------
__device__ float g_q[BH * SEQ * HDIM];
__device__ float g_k[BH * SEQ * HDIM];
__device__ float g_v[BH * SEQ * HDIM];
__device__ float g_ao[BATCH * SEQ * CDIM];     // pair-packed along CDIM
__device__ float g_xp[BATCH * SEQ * CDIM];
__device__ float g_wp[4 * CDIM * CDIM];

// ---------------------------------------------------------------------------
__device__ __forceinline__ float tf32r(float x) {
    uint32_t u; asm("cvt.rna.tf32.f32 %0, %1;" : "=r"(u) : "f"(x));
    return __uint_as_float(u);
}
__device__ __forceinline__ float ex2f(float x) {
    float r; asm("ex2.approx.ftz.f32 %0, %1;" : "=f"(r) : "f"(x));
    return r;
}
__device__ __forceinline__ uint32_t smem_u32(const void* p) {
    uint32_t a;
    asm("{ .reg .u64 t; cvta.to.shared.u64 t, %1; cvt.u32.u64 %0, t; }" : "=r"(a) : "l"(p));
    return a;
}
__device__ __forceinline__ void cpa16(uint32_t dst, const float* src) {
    asm volatile("cp.async.cg.shared.global [%0], [%1], 16;" :: "r"(dst), "l"(src) : "memory");
}
__device__ __forceinline__ void mma_tf32(float (&c)[4], const uint32_t (&a)[4],
                                         uint32_t b0, uint32_t b1) {
    asm("mma.sync.aligned.m16n8k8.row.col.f32.tf32.tf32.f32 "
        "{%0,%1,%2,%3}, {%4,%5,%6,%7}, {%8,%9}, {%0,%1,%2,%3};"
        : "+f"(c[0]), "+f"(c[1]), "+f"(c[2]), "+f"(c[3])
        : "r"(a[0]), "r"(a[1]), "r"(a[2]), "r"(a[3]), "r"(b0), "r"(b1));
}
__device__ __forceinline__ int dpack(int d) {
    return (d & ~7) | ((d & 3) << 1) | ((d >> 2) & 1);
}

// ---------------------------------------------------------------------------
// Prepass: tf32-round + pair-pack x and the four weight matrices.
// ---------------------------------------------------------------------------
__global__ void pack_tf32(const float* __restrict__ x,
                          const float* __restrict__ Wq,
                          const float* __restrict__ Wk,
                          const float* __restrict__ Wv,
                          const float* __restrict__ Wp)
{
    int i = blockIdx.x * 256 + threadIdx.x;
    if (i >= PACKTOT) return;
    const float* src;
    float* dst;
    if (i < XGROUPS) {
        src = x; dst = g_xp;
    } else {
        int j = i - XGROUPS;
        int w = j >> 13;
        i = j & (WGROUPS - 1);
        src = (w == 0) ? Wq : (w == 1) ? Wk : (w == 2) ? Wv : Wp;
        dst = g_wp + w * (CDIM * CDIM);
    }
    float4 a = ((const float4*)src)[i * 2];
    float4 b = ((const float4*)src)[i * 2 + 1];
    float4 o0 = make_float4(tf32r(a.x), tf32r(b.x), tf32r(a.y), tf32r(b.y));
    float4 o1 = make_float4(tf32r(a.z), tf32r(b.z), tf32r(a.w), tf32r(b.w));
    ((float4*)dst)[i * 2]     = o0;
    ((float4*)dst)[i * 2 + 1] = o1;
}

// ---------------------------------------------------------------------------
// tf32 mma projection core on PACKED operands
// ---------------------------------------------------------------------------
struct ProjAcc { float c[2][8][4]; };

__device__ __forceinline__ void proj_core(const float* __restrict__ A,
                                          const float* __restrict__ Bm,
                                          int m0, int n0, float* smp, ProjAcc& P)
{
    const int tid = threadIdx.x, lane = tid & 31, warp = tid >> 5;
    const int g = lane >> 2, qd = lane & 3;
    const int wm = warp >> 1, wn = warp & 1;
    const uint32_t smb = smem_u32(smp);

    #pragma unroll
    for (int m = 0; m < 2; m++)
        #pragma unroll
        for (int nn = 0; nn < 8; nn++)
            #pragma unroll
            for (int i = 0; i < 4; i++) P.c[m][nn][i] = 0.f;

    auto stage = [&](int kc, int b) {
        uint32_t xb = smb + (uint32_t)(b * PBUF) * 4;
        uint32_t wb = xb + (uint32_t)(128 * PSTR2 * 2) * 4;
        int k0 = kc * 32;
        #pragma unroll
        for (int p = 0; p < 4; p++) {
            int idx = p * 256 + tid;
            int r = idx >> 3, cc = idx & 7;
            cpa16(xb + (uint32_t)(r * (PSTR2 * 2) + cc * 4) * 4,
                  A  + (size_t)(m0 + r) * CDIM + k0 + cc * 4);
            cpa16(wb + (uint32_t)(r * (PSTR2 * 2) + cc * 4) * 4,
                  Bm + (size_t)(n0 + r) * CDIM + k0 + cc * 4);
        }
    };

    stage(0, 0);
    asm volatile("cp.async.commit_group;" ::: "memory");

    for (int kc = 0; kc < CDIM / 32; kc++) {
        int b = kc & 1;
        if (kc + 1 < CDIM / 32) {
            stage(kc + 1, b ^ 1);
            asm volatile("cp.async.commit_group;" ::: "memory");
            asm volatile("cp.async.wait_group 1;" ::: "memory");
        } else {
            asm volatile("cp.async.wait_group 0;" ::: "memory");
        }
        __syncthreads();

        const float2* Xs2 = (const float2*)(smp + b * PBUF);
        const float2* Ws2 = Xs2 + 128 * PSTR2;

        #pragma unroll
        for (int kk = 0; kk < 4; kk++) {
            uint32_t am[2][4];
            #pragma unroll
            for (int m = 0; m < 2; m++) {
                int r0 = wm * 32 + m * 16;
                float2 qa = Xs2[(r0 + g    ) * PSTR2 + kk * 4 + qd];
                float2 qb = Xs2[(r0 + g + 8) * PSTR2 + kk * 4 + qd];
                am[m][0] = __float_as_uint(qa.x);
                am[m][1] = __float_as_uint(qb.x);
                am[m][2] = __float_as_uint(qa.y);
                am[m][3] = __float_as_uint(qb.y);
            }
            #pragma unroll
            for (int nn = 0; nn < 8; nn++) {
                float2 bb = Ws2[(wn * 64 + nn * 8 + g) * PSTR2 + kk * 4 + qd];
                uint32_t b0 = __float_as_uint(bb.x);
                uint32_t b1 = __float_as_uint(bb.y);
                mma_tf32(P.c[0][nn], am[0], b0, b1);
                mma_tf32(P.c[1][nn], am[1], b0, b1);
            }
        }
        __syncthreads();
    }
}

// grid (2, 128, 3)
__global__ void __launch_bounds__(256) proj_qkv()
{
    extern __shared__ float smp[];
    const int z = blockIdx.z;
    const float* W = g_wp + z * (CDIM * CDIM);
    float* dst     = (z == 0) ? g_q : (z == 1) ? g_k : g_v;
    // fold log2e into Q so attention can use raw ex2
    const float sc = (z == 0) ? (SCALE * LOG2E) : 1.0f;
    const int m0 = blockIdx.y * 128, n0 = blockIdx.x * 128;

    ProjAcc P;
    proj_core(g_xp, W, m0, n0, smp, P);

    const int lane = threadIdx.x & 31, warp = threadIdx.x >> 5;
    const int g = lane >> 2, qd = lane & 3;
    const int wm = warp >> 1, wn = warp & 1;

    #pragma unroll
    for (int m = 0; m < 2; m++)
        #pragma unroll
        for (int rr = 0; rr < 2; rr++) {
            int mg = m0 + wm * 32 + m * 16 + g + rr * 8;
            int b = mg >> 12, n = mg & (SEQ - 1);
            #pragma unroll
            for (int nn = 0; nn < 8; nn++) {
                int col = n0 + wn * 64 + nn * 8 + qd * 2;
                int h = col >> 6, d = col & 63;
                float v0 = tf32r(P.c[m][nn][rr * 2 + 0] * sc);
                float v1 = tf32r(P.c[m][nn][rr * 2 + 1] * sc);
                size_t bh = (size_t)(b * HEADS + h);
                if (z < 2) {
                    float* rowp = dst + (bh * SEQ + n) * HDIM;
                    rowp[dpack(d)]     = v0;
                    rowp[dpack(d + 1)] = v1;
                } else {
                    float* vp = dst + (bh * (SEQ / 2) + (n >> 1)) * (HDIM * 2) + (n & 1);
                    vp[d * 2]       = v0;
                    vp[(d + 1) * 2] = v1;
                }
            }
        }
}

// grid (2, 128)
__global__ void __launch_bounds__(256) proj_out(const float* __restrict__ bp,
                                                float* __restrict__ out)
{
    extern __shared__ float smp[];
    const int m0 = blockIdx.y * 128, n0 = blockIdx.x * 128;

    ProjAcc P;
    proj_core(g_ao, g_wp + 3 * (CDIM * CDIM), m0, n0, smp, P);

    const int lane = threadIdx.x & 31, warp = threadIdx.x >> 5;
    const int g = lane >> 2, qd = lane & 3;
    const int wm = warp >> 1, wn = warp & 1;

    #pragma unroll
    for (int m = 0; m < 2; m++)
        #pragma unroll
        for (int rr = 0; rr < 2; rr++) {
            int mg = m0 + wm * 32 + m * 16 + g + rr * 8;
            #pragma unroll
            for (int nn = 0; nn < 8; nn++) {
                int col = n0 + wn * 64 + nn * 8 + qd * 2;
                float2 bb = *(const float2*)(bp + col);
                float2 v = make_float2(P.c[m][nn][rr * 2 + 0] + bb.x,
                                       P.c[m][nn][rr * 2 + 1] + bb.y);
                *(float2*)&out[(size_t)mg * CDIM + col] = v;
            }
        }
}

// ---------------------------------------------------------------------------
// tf32 mma.sync flash attention: 3-stage cp.async pipeline, one barrier per
// tile, shuffle-free P feed, ex2-based softmax (log2e pre-folded into Q).
// grid = (SEQ/128, BH), block = 128, 2 CTAs/SM
// ---------------------------------------------------------------------------
__global__ void __launch_bounds__(128, 2) attn_mma()
{
    extern __shared__ float sm[];
    const int tid = threadIdx.x, lane = tid & 31, warp = tid >> 5;
    const int g = lane >> 2, qd = lane & 3;
    const int bh = blockIdx.y, q0 = blockIdx.x * 128;

    const float2* qg2 = (const float2*)(g_q + ((size_t)bh * SEQ + q0 + warp * 32) * HDIM);
    const float*  kg  = g_k + (size_t)bh * SEQ * HDIM;
    const float*  vgp = g_v + (size_t)bh * SEQ * HDIM;

    uint32_t qf[2][8][4];
    #pragma unroll
    for (int m = 0; m < 2; m++)
        #pragma unroll
        for (int kk = 0; kk < 8; kk++) {
            float2 qa = qg2[(m * 16 + g    ) * 32 + kk * 4 + qd];
            float2 qb = qg2[(m * 16 + g + 8) * 32 + kk * 4 + qd];
            qf[m][kk][0] = __float_as_uint(qa.x);
            qf[m][kk][1] = __float_as_uint(qb.x);
            qf[m][kk][2] = __float_as_uint(qa.y);
            qf[m][kk][3] = __float_as_uint(qb.y);
        }

    float o[2][8][4] = {};
    float ls[4] = {0.f, 0.f, 0.f, 0.f};

    const uint32_t smb = smem_u32(sm);

    auto stage = [&](int t4, int buf) {
        uint32_t kdst = smb + (uint32_t)buf * BUFBYTES;
        uint32_t vdst = kdst + KBYTES;
        int j0 = t4 * TK;
        #pragma unroll
        for (int i = 0; i < 8; i++) {
            int idx = i * 128 + tid;
            int r = idx >> 4, c = idx & 15;
            cpa16(kdst + (uint32_t)(r * KSTR + c * 4) * 4, kg + (size_t)(j0 + r) * 64 + c * 4);
            int r2 = idx >> 5, c2 = idx & 31;
            cpa16(vdst + (uint32_t)(r2 * (VSTR2 * 2) + c2 * 4) * 4,
                  vgp + (size_t)(j0 / 2 + r2) * 128 + c2 * 4);
        }
    };

    stage(0, 0);
    asm volatile("cp.async.commit_group;" ::: "memory");
    stage(1, 1);
    asm volatile("cp.async.commit_group;" ::: "memory");

    int buf = 0;        // buffer holding tile t
    int bnext = 2;      // buffer to stage tile t+2 into

    for (int t = 0; t < NT; t++) {
        if (t < NT - 1) {
            asm volatile("cp.async.wait_group 1;" ::: "memory");
        } else {
            asm volatile("cp.async.wait_group 0;" ::: "memory");
        }
        __syncthreads();   // tile t visible to all warps; frees buffer bnext

        if (t + 2 < NT) {
            stage(t + 2, bnext);
            asm volatile("cp.async.commit_group;" ::: "memory");
        }

        const float*  Ks  = sm + buf * (BUFBYTES / 4);
        const float2* Vs2 = (const float2*)(Ks + KBYTES / 4);

        #pragma unroll
        for (int nn = 0; nn < 8; nn++) {
            float c0a[4] = {}, c0b[4] = {}, c1a[4] = {}, c1b[4] = {};
            const float2* kb2 = (const float2*)Ks + (nn * 8 + g) * (KSTR / 2) + qd;
            #pragma unroll
            for (int kk = 0; kk < 4; kk++) {
                float2 b01 = kb2[kk * 4];
                uint32_t b0 = __float_as_uint(b01.x);
                uint32_t b1 = __float_as_uint(b01.y);
                mma_tf32(c0a, qf[0][kk], b0, b1);
                mma_tf32(c1a, qf[1][kk], b0, b1);
            }
            #pragma unroll
            for (int kk = 4; kk < 8; kk++) {
                float2 b01 = kb2[kk * 4];
                uint32_t b0 = __float_as_uint(b01.x);
                uint32_t b1 = __float_as_uint(b01.y);
                mma_tf32(c0b, qf[0][kk], b0, b1);
                mma_tf32(c1b, qf[1][kk], b0, b1);
            }

            // logits are pre-scaled by log2e -> raw ex2
            float e0[4], e1[4];
            #pragma unroll
            for (int i = 0; i < 4; i++) {
                e0[i] = ex2f(c0a[i] + c0b[i]);
                e1[i] = ex2f(c1a[i] + c1b[i]);
            }
            ls[0] += e0[0] + e0[1];  ls[1] += e0[2] + e0[3];
            ls[2] += e1[0] + e1[1];  ls[3] += e1[2] + e1[3];

            uint32_t pa0[4], pa1[4];
            pa0[0] = __float_as_uint(e0[0]); pa0[1] = __float_as_uint(e0[2]);
            pa0[2] = __float_as_uint(e0[1]); pa0[3] = __float_as_uint(e0[3]);
            pa1[0] = __float_as_uint(e1[0]); pa1[1] = __float_as_uint(e1[2]);
            pa1[2] = __float_as_uint(e1[1]); pa1[3] = __float_as_uint(e1[3]);

            const float2* vb2 = Vs2 + (nn * 4 + qd) * VSTR2 + g;
            #pragma unroll
            for (int dn = 0; dn < 8; dn++) {
                float2 v01 = vb2[dn * 8];
                uint32_t b0 = __float_as_uint(v01.x);
                uint32_t b1 = __float_as_uint(v01.y);
                mma_tf32(o[0][dn], pa0, b0, b1);
                mma_tf32(o[1][dn], pa1, b0, b1);
            }
        }

        buf = (buf == 2) ? 0 : buf + 1;
        bnext = (bnext == 2) ? 0 : bnext + 1;
    }

    #pragma unroll
    for (int i = 0; i < 4; i++) {
        ls[i] += __shfl_xor_sync(0xffffffffu, ls[i], 1);
        ls[i] += __shfl_xor_sync(0xffffffffu, ls[i], 2);
    }

    const int b = bh >> 2, h = bh & 3;
    #pragma unroll
    for (int m = 0; m < 2; m++)
        #pragma unroll
        for (int rr = 0; rr < 2; rr++) {
            int row = q0 + warp * 32 + m * 16 + g + rr * 8;
            float iv = 1.f / ls[m * 2 + rr];
            float* aop = g_ao + ((size_t)(b * SEQ) + row) * CDIM + h * 64;
            #pragma unroll
            for (int dn = 0; dn < 8; dn++) {
                int d = dn * 8 + qd * 2;
                aop[(dn * 8) + dpack(d & 7)]       = tf32r(o[m][dn][rr * 2 + 0] * iv);
                aop[(dn * 8) + dpack((d + 1) & 7)] = tf32r(o[m][dn][rr * 2 + 1] * iv);
            }
        }
}

// ---------------------------------------------------------------------------
extern "C" void kernel_launch(void* const* d_in, const int* in_sizes, int n_in,
                              void* d_out, int out_size)
{
    (void)in_sizes; (void)n_in; (void)out_size;
    const float* x  = (const float*)d_in[0];
    const float* Wq = (const float*)d_in[1];
    const float* Wk = (const float*)d_in[2];
    const float* Wv = (const float*)d_in[3];
    const float* Wp = (const float*)d_in[4];
    const float* bp = (const float*)d_in[5];
    float* out = (float*)d_out;

    cudaFuncSetAttribute(proj_qkv, cudaFuncAttributeMaxDynamicSharedMemorySize, SMEM_PROJ);
    cudaFuncSetAttribute(proj_out, cudaFuncAttributeMaxDynamicSharedMemorySize, SMEM_PROJ);
    cudaFuncSetAttribute(attn_mma, cudaFuncAttributeMaxDynamicSharedMemorySize, SMEM_ATTN);

    pack_tf32<<<(PACKTOT + 255) / 256, 256>>>(x, Wq, Wk, Wv, Wp);

    dim3 gq(CDIM / 128, (BATCH * SEQ) / 128, 3);
    proj_qkv<<<gq, 256, SMEM_PROJ>>>();

    dim3 ga(SEQ / 128, BH);
    attn_mma<<<ga, 128, SMEM_ATTN>>>();

    dim3 go(CDIM / 128, (BATCH * SEQ) / 128);
    proj_out<<<go, 256, SMEM_PROJ>>>(bp, out);
}